// round 10
// baseline (speedup 1.0000x reference)
#include <cuda_runtime.h>
#include <cstdint>

#define BB 4
#define CC 512
#define HH 56
#define NQ 3136
#define OQ 784
#define NH 8
#define HD 64
#define LEPS 1e-5f

#define BM 128
#define BN 64
#define BK 16

static __device__ __align__(256) float g_xf[(size_t)BB*NQ*CC];
static __device__ __align__(256) float g_xs[(size_t)BB*OQ*CC];
static __device__ __align__(256) float g_qb[(size_t)BB*NQ*CC];
static __device__ __align__(256) float g_kb[(size_t)BB*OQ*CC];
static __device__ __align__(256) float g_vt[(size_t)BB*CC*OQ];
static __device__ __align__(256) float g_attn[(size_t)BB*NH*NQ*OQ];  // ~315 MB
static __device__ __align__(256) float g_ao[(size_t)BB*NQ*CC];
static __device__ __align__(256) float g_wr[4*CC*CC];                // rounded weights
static __device__ float g_pssq[(size_t)BB*NH*NQ];
static __device__ float g_rstd[BB*NH];

__device__ __forceinline__ float tf32r(float x) {
    uint32_t u;
    asm("cvt.rna.tf32.f32 %0, %1;" : "=r"(u) : "f"(x));
    return __uint_as_float(u);
}
__device__ __forceinline__ uint32_t s2u(const void* p) {
    return (uint32_t)__cvta_generic_to_shared(p);
}
#define CP16(dst, src) \
    asm volatile("cp.async.cg.shared.global [%0], [%1], 16;" :: "r"(dst), "l"(src))
#define CPCOMMIT() asm volatile("cp.async.commit_group;")
#define CPWAIT(N) asm volatile("cp.async.wait_group %0;" :: "n"(N))

// ---------------------------------------------------------------------------
// Round the 4 weight matrices to tf32 once per launch.
// ---------------------------------------------------------------------------
__global__ void k_wround(const float* __restrict__ qw, const float* __restrict__ kw,
                         const float* __restrict__ vw, const float* __restrict__ pw) {
    int i = blockIdx.x * 1024 + threadIdx.x;
    g_wr[i]               = tf32r(qw[i]);
    g_wr[CC*CC + i]       = tf32r(kw[i]);
    g_wr[2*CC*CC + i]     = tf32r(vw[i]);
    g_wr[3*CC*CC + i]     = tf32r(pw[i]);
}

// ---------------------------------------------------------------------------
// Transpose x (B,C,NQ) -> xf (B,NQ,C), rounded to tf32
// ---------------------------------------------------------------------------
__global__ void k_transpose(const float* __restrict__ x) {
    __shared__ float t[32][33];
    int b = blockIdx.z;
    int q0 = blockIdx.x * 32, c0 = blockIdx.y * 32;
    int tx = threadIdx.x, ty = threadIdx.y;
#pragma unroll
    for (int i = 0; i < 32; i += 8)
        t[ty + i][tx] = x[((size_t)b * CC + c0 + ty + i) * NQ + q0 + tx];
    __syncthreads();
#pragma unroll
    for (int i = 0; i < 32; i += 8)
        g_xf[((size_t)b * NQ + q0 + ty + i) * CC + c0 + tx] = tf32r(t[tx][ty + i]);
}

// ---------------------------------------------------------------------------
// Depthwise 3x3 s2 p1 conv + bias -> g_xs (B,OQ,C)
// ---------------------------------------------------------------------------
__global__ void k_conv(const float* __restrict__ x, const float* __restrict__ w,
                       const float* __restrict__ bias) {
    int bc = blockIdx.x;
    int b = bc >> 9;
    int c = bc & 511;
    __shared__ float sx[HH * HH];
    const float* xp = x + ((size_t)b * CC + c) * NQ;
    for (int i = threadIdx.x; i < HH * HH; i += 256) sx[i] = xp[i];
    float w0 = w[c*9+0], w1 = w[c*9+1], w2 = w[c*9+2];
    float w3 = w[c*9+3], w4 = w[c*9+4], w5 = w[c*9+5];
    float w6 = w[c*9+6], w7 = w[c*9+7], w8 = w[c*9+8];
    float bi = bias[c];
    __syncthreads();
    for (int o = threadIdx.x; o < OQ; o += 256) {
        int oy = o / 28, ox = o - oy * 28;
        int y0 = oy * 2 - 1, x0 = ox * 2 - 1;
        float s = bi;
        if (y0 >= 0) {
            const float* r = &sx[y0 * HH];
            if (x0 >= 0) s += r[x0] * w0;
            s += r[x0 + 1] * w1 + r[x0 + 2] * w2;
        }
        {
            const float* r = &sx[(y0 + 1) * HH];
            if (x0 >= 0) s += r[x0] * w3;
            s += r[x0 + 1] * w4 + r[x0 + 2] * w5;
        }
        {
            const float* r = &sx[(y0 + 2) * HH];
            if (x0 >= 0) s += r[x0] * w6;
            s += r[x0 + 1] * w7 + r[x0 + 2] * w8;
        }
        g_xs[((size_t)b * OQ + o) * CC + c] = s;
    }
}

// ---------------------------------------------------------------------------
// LayerNorm over C=512 per row, in place, output rounded to tf32
// ---------------------------------------------------------------------------
__global__ void k_ln(const float* __restrict__ gam, const float* __restrict__ bet) {
    int row = blockIdx.x;
    float* p = g_xs + (size_t)row * CC;
    int tid = threadIdx.x;
    float v0 = p[tid], v1 = p[tid + 256];
    float s = v0 + v1, sq = v0 * v0 + v1 * v1;
    __shared__ float r1[8], r2[8];
    __shared__ float s_m, s_r;
#pragma unroll
    for (int off = 16; off; off >>= 1) {
        s  += __shfl_xor_sync(0xffffffffu, s, off);
        sq += __shfl_xor_sync(0xffffffffu, sq, off);
    }
    if ((tid & 31) == 0) { r1[tid >> 5] = s; r2[tid >> 5] = sq; }
    __syncthreads();
    if (tid == 0) {
        float S = 0.f, Q = 0.f;
        for (int i = 0; i < 8; i++) { S += r1[i]; Q += r2[i]; }
        float mean = S * (1.f / CC);
        float var = Q * (1.f / CC) - mean * mean;
        s_m = mean;
        s_r = rsqrtf(var + LEPS);
    }
    __syncthreads();
    float mean = s_m, rs = s_r;
    p[tid]       = tf32r((v0 - mean) * rs * gam[tid]       + bet[tid]);
    p[tid + 256] = tf32r((v1 - mean) * rs * gam[tid + 256] + bet[tid + 256]);
}

// ---------------------------------------------------------------------------
// TF32 NT GEMM, cp.async 4-stage pipeline. Inputs MUST be pre-rounded tf32.
// C[m,n] = alpha * sum_k A[m,k]*W[n,k] (+bias). Batched over blockIdx.z.
// ---------------------------------------------------------------------------
#define A_ST_F (16 * BM)     // floats per A stage (2048)
#define B_ST_F (16 * BN)     // floats per B stage (1024)

template <bool TRANS_OUT, bool HAS_BIAS, bool ROUND_OUT, bool ALPHA_PTR>
__global__ void __launch_bounds__(256)
k_mma2(const float* __restrict__ A, int lda, long long sAb, long long sAh,
       const float* __restrict__ W, int ldw, long long sWb, long long sWh,
       float* __restrict__ Cp, int ldc, long long sCb, long long sCh,
       int M, int N, int K, float alpha, const float* __restrict__ bias,
       int trows, const float* __restrict__ alphap) {
    __shared__ float As[4][A_ST_F];   // 32 KB
    __shared__ float Bs[4][B_ST_F];   // 16 KB

    int bz = blockIdx.z;
    A  += (long long)(bz >> 3) * sAb + (long long)(bz & 7) * sAh;
    W  += (long long)(bz >> 3) * sWb + (long long)(bz & 7) * sWh;
    Cp += (long long)(bz >> 3) * sCb + (long long)(bz & 7) * sCh;
    if (ALPHA_PTR) alpha = alphap[bz];

    int m0 = blockIdx.y * BM, n0 = blockIdx.x * BN;
    int tid = threadIdx.x;
    int lane = tid & 31, warp = tid >> 5;
    int wm = (warp & 3) * 32, wn = (warp >> 2) * 32;
    int gid = lane >> 2, tig = lane & 3;
    int lk4 = tid & 3, lrow = tid >> 2;

    int gmA0 = min(m0 + lrow, M - 1);
    int gmA1 = min(m0 + lrow + 64, M - 1);
    int gnB  = min(n0 + lrow, N - 1);
    const float* pA0 = A + (size_t)gmA0 * lda + lk4 * 4;
    const float* pA1 = A + (size_t)gmA1 * lda + lk4 * 4;
    const float* pB  = W + (size_t)gnB * ldw + lk4 * 4;

    uint32_t sA0 = s2u(&As[0][(lk4 * BM + (lrow ^ (lk4 << 1))) * 4]);
    uint32_t sA1 = sA0 + 64 * 16;
    uint32_t sB  = s2u(&Bs[0][(lk4 * BN + (lrow ^ (lk4 << 1))) * 4]);

    const float* fA[4];
    const float* fB[4];
#pragma unroll
    for (int k4 = 0; k4 < 4; k4++) {
        int gx = gid ^ (k4 << 1);
        fA[k4] = &As[0][(k4 * BM + wm + gx) * 4 + tig];
        fB[k4] = &Bs[0][(k4 * BN + wn + gx) * 4 + tig];
    }

    float acc[2][4][4];
#pragma unroll
    for (int i = 0; i < 2; i++)
#pragma unroll
        for (int j = 0; j < 4; j++)
#pragma unroll
            for (int l = 0; l < 4; l++) acc[i][j][l] = 0.f;

#define ISSUE(S)                                                               \
    {                                                                          \
        CP16(sA0 + (S) * (A_ST_F * 4), pA0);                                   \
        CP16(sA1 + (S) * (A_ST_F * 4), pA1);                                   \
        CP16(sB + (S) * (B_ST_F * 4), pB);                                     \
        pA0 += BK; pA1 += BK; pB += BK;                                        \
    }

    int nkb = K / BK;
    ISSUE(0); CPCOMMIT();
    ISSUE(1); CPCOMMIT();
    ISSUE(2); CPCOMMIT();

    for (int kb = 0; kb < nkb; kb++) {
        CPWAIT(2);
        __syncthreads();
        int st = kb & 3;
        if (kb + 3 < nkb) {
            int sn = (kb + 3) & 3;
            ISSUE(sn);
        }
        CPCOMMIT();
        int aoff = st * A_ST_F, boff = st * B_ST_F;
#pragma unroll
        for (int ks = 0; ks < 2; ks++) {
            const float* a0p = fA[2 * ks] + aoff;
            const float* a1p = fA[2 * ks + 1] + aoff;
            const float* b0p = fB[2 * ks] + boff;
            const float* b1p = fB[2 * ks + 1] + boff;
            uint32_t af[2][4], bf[4][2];
#pragma unroll
            for (int mi = 0; mi < 2; mi++) {
                af[mi][0] = __float_as_uint(a0p[mi * 64]);
                af[mi][1] = __float_as_uint(a0p[mi * 64 + 32]);
                af[mi][2] = __float_as_uint(a1p[mi * 64]);
                af[mi][3] = __float_as_uint(a1p[mi * 64 + 32]);
            }
#pragma unroll
            for (int ni = 0; ni < 4; ni++) {
                bf[ni][0] = __float_as_uint(b0p[ni * 32]);
                bf[ni][1] = __float_as_uint(b1p[ni * 32]);
            }
#pragma unroll
            for (int mi = 0; mi < 2; mi++)
#pragma unroll
            for (int ni = 0; ni < 4; ni++) {
                asm volatile(
                    "mma.sync.aligned.m16n8k8.row.col.f32.tf32.tf32.f32 "
                    "{%0,%1,%2,%3}, {%4,%5,%6,%7}, {%8,%9}, {%0,%1,%2,%3};"
                    : "+f"(acc[mi][ni][0]), "+f"(acc[mi][ni][1]),
                      "+f"(acc[mi][ni][2]), "+f"(acc[mi][ni][3])
                    : "r"(af[mi][0]), "r"(af[mi][1]),
                      "r"(af[mi][2]), "r"(af[mi][3]),
                      "r"(bf[ni][0]), "r"(bf[ni][1]));
            }
        }
    }
#undef ISSUE

#pragma unroll
    for (int mi = 0; mi < 2; mi++)
#pragma unroll
    for (int ni = 0; ni < 4; ni++) {
        int r0 = m0 + wm + mi * 16 + gid;
        int c0 = n0 + wn + ni * 8 + tig * 2;
#pragma unroll
        for (int half = 0; half < 2; half++) {
            int r = r0 + half * 8;
            if (r >= M) continue;
#pragma unroll
            for (int cc2 = 0; cc2 < 2; cc2++) {
                int c = c0 + cc2;
                if (c >= N) continue;
                float vv = acc[mi][ni][half * 2 + cc2] * alpha;
                if (HAS_BIAS) vv += bias[c];
                if (ROUND_OUT) vv = tf32r(vv);
                if (TRANS_OUT) {
                    int bidx = r / trows, q = r - bidx * trows;
                    Cp[((long long)bidx * N + c) * trows + q] = vv;
                } else {
                    Cp[(long long)r * ldc + c] = vv;
                }
            }
        }
    }
}

// ---------------------------------------------------------------------------
// Specialized QK logits kernel, cp.async version. Q-tile resident; stream
// 64-row K-chunks double-buffered. Inputs pre-rounded tf32.
// ---------------------------------------------------------------------------
#define NCH ((OQ + 63) / 64)   // 13

__global__ void __launch_bounds__(256, 2)
k_qk(const float* __restrict__ Qm, const float* __restrict__ Km,
     float* __restrict__ attn) {
    __shared__ float Aq[16 * 128 * 4];       // 32 KB
    __shared__ float Bk[2][16 * 64 * 4];     // 2 x 16 KB

    int z = blockIdx.y;
    int b = z >> 3, h = z & 7;
    int q0 = blockIdx.x * 128;
    const float* Qp = Qm + (size_t)b * NQ * CC + h * HD;
    const float* Kp = Km + (size_t)b * OQ * CC + h * HD;
    float* Op = attn + (size_t)z * NQ * OQ;

    int tid = threadIdx.x;
    int lane = tid & 31, warp = tid >> 5;
    int wm = (warp & 3) * 32, wn = (warp >> 2) * 32;
    int gid = lane >> 2, tig = lane & 3;
    int lk4 = tid & 3, lrow = tid >> 2;

    uint32_t aqb = s2u(Aq);
    uint32_t bkb = s2u(Bk);

    // resident Q via cp.async
#pragma unroll
    for (int kt = 0; kt < 4; kt++)
#pragma unroll
        for (int it = 0; it < 2; it++) {
            int r = lrow + it * 64;
            int gm = min(q0 + r, NQ - 1);
            uint32_t dst = aqb + ((kt * 4 + lk4) * 128 + (r ^ (lk4 << 1))) * 16;
            CP16(dst, Qp + (size_t)gm * CC + kt * 16 + lk4 * 4);
        }

#define ISSUEB(J, BUF)                                                         \
    {                                                                          \
        int go = min((J) * 64 + lrow, OQ - 1);                                 \
        const float* src = Kp + (size_t)go * CC + lk4 * 4;                     \
        uint32_t dst0 = bkb + (BUF) * 16384 +                                  \
                        (lk4 * 64 + (lrow ^ (lk4 << 1))) * 16;                 \
        _Pragma("unroll")                                                      \
        for (int kt = 0; kt < 4; kt++)                                         \
            CP16(dst0 + kt * 4096, src + kt * 16);                             \
    }

    ISSUEB(0, 0);
    CPCOMMIT();

    for (int j = 0; j < NCH; j++) {
        CPWAIT(0);
        __syncthreads();
        if (j + 1 < NCH) {
            ISSUEB(j + 1, (j + 1) & 1);
            CPCOMMIT();
        }

        float acc[2][4][4];
#pragma unroll
        for (int i = 0; i < 2; i++)
#pragma unroll
            for (int jj = 0; jj < 4; jj++)
#pragma unroll
                for (int l = 0; l < 4; l++) acc[i][jj][l] = 0.f;

        const float* Af = Aq;
        const float* Bf = Bk[j & 1];
#pragma unroll
        for (int ks = 0; ks < 8; ks++) {
            const int k4a = 2 * ks, k4b = 2 * ks + 1;
            const int ca = (k4a & 3) << 1, cb = (k4b & 3) << 1;
            uint32_t af[2][4], bf[4][2];
#pragma unroll
            for (int mi = 0; mi < 2; mi++) {
                int ra = (wm + mi * 16 + gid) ^ ca;
                int rb2 = (wm + mi * 16 + gid) ^ cb;
                af[mi][0] = __float_as_uint(Af[(k4a * 128 + ra) * 4 + tig]);
                af[mi][1] = __float_as_uint(Af[(k4a * 128 + ra + 8) * 4 + tig]);
                af[mi][2] = __float_as_uint(Af[(k4b * 128 + rb2) * 4 + tig]);
                af[mi][3] = __float_as_uint(Af[(k4b * 128 + rb2 + 8) * 4 + tig]);
            }
#pragma unroll
            for (int ni = 0; ni < 4; ni++) {
                int na = (wn + ni * 8 + gid) ^ ca;
                int nb = (wn + ni * 8 + gid) ^ cb;
                bf[ni][0] = __float_as_uint(Bf[((k4a & 3) * 64 + na) * 4 + tig +
                                               (k4a >> 2) * 1024]);
                bf[ni][1] = __float_as_uint(Bf[((k4b & 3) * 64 + nb) * 4 + tig +
                                               (k4b >> 2) * 1024]);
            }
#pragma unroll
            for (int mi = 0; mi < 2; mi++)
#pragma unroll
            for (int ni = 0; ni < 4; ni++) {
                asm volatile(
                    "mma.sync.aligned.m16n8k8.row.col.f32.tf32.tf32.f32 "
                    "{%0,%1,%2,%3}, {%4,%5,%6,%7}, {%8,%9}, {%0,%1,%2,%3};"
                    : "+f"(acc[mi][ni][0]), "+f"(acc[mi][ni][1]),
                      "+f"(acc[mi][ni][2]), "+f"(acc[mi][ni][3])
                    : "r"(af[mi][0]), "r"(af[mi][1]),
                      "r"(af[mi][2]), "r"(af[mi][3]),
                      "r"(bf[ni][0]), "r"(bf[ni][1]));
            }
        }

        int o0 = j * 64;
#pragma unroll
        for (int mi = 0; mi < 2; mi++)
#pragma unroll
        for (int ni = 0; ni < 4; ni++) {
            int r0 = q0 + wm + mi * 16 + gid;
            int c0 = o0 + wn + ni * 8 + tig * 2;
#pragma unroll
            for (int half = 0; half < 2; half++) {
                int r = r0 + half * 8;
                if (r >= NQ) continue;
#pragma unroll
                for (int cc2 = 0; cc2 < 2; cc2++) {
                    int c = c0 + cc2;
                    if (c >= OQ) continue;
                    Op[(size_t)r * OQ + c] = acc[mi][ni][half * 2 + cc2] * 0.125f;
                }
            }
        }
    }
#undef ISSUEB
}

// ---------------------------------------------------------------------------
// Fused head-mix + softmax; writes t = tf32r((a - 1/OQ) * aw) in place, plus
// per-row sum(a^2) partials. InstanceNorm rstd applied later as GEMM alpha.
// ---------------------------------------------------------------------------
__global__ void __launch_bounds__(256)
k_mixsoftmax(const float* __restrict__ tcw, const float* __restrict__ tcb,
             const float* __restrict__ aw) {
    int bq = blockIdx.x;
    int b = bq / NQ;
    int q = bq - b * NQ;
    int tid = threadIdx.x;
    int lane = tid & 31, wid = tid >> 5;
    __shared__ float s_w[64];
    __shared__ float s_b[8];
    __shared__ float srA[8][8];
    __shared__ float srB[8][8];
    __shared__ float gmaxs[8];
    __shared__ float ginv[8];
    __shared__ float gssq[8];
    if (tid < 64) s_w[tid] = tcw[tid];
    if (tid < 8)  s_b[tid] = tcb[tid];
    __syncthreads();
    const long long HS = (long long)NQ * OQ;
    const float amean = 1.f / OQ;
    long long base0 = (long long)b * NH * HS + (long long)q * OQ;
    float m[8][4];
#pragma unroll
    for (int j = 0; j < 4; j++) {
        int o = tid + j * 256;
        bool valid = o < OQ;
        float lh[8];
#pragma unroll
        for (int h = 0; h < 8; h++)
            lh[h] = valid ? g_attn[base0 + (long long)h * HS + o] : 0.f;
#pragma unroll
        for (int g2 = 0; g2 < 8; g2++) {
            float s = s_b[g2];
#pragma unroll
            for (int h = 0; h < 8; h++) s += s_w[g2 * 8 + h] * lh[h];
            m[g2][j] = valid ? s : -1e30f;
        }
    }
    float lm[8];
#pragma unroll
    for (int g2 = 0; g2 < 8; g2++)
        lm[g2] = fmaxf(fmaxf(m[g2][0], m[g2][1]), fmaxf(m[g2][2], m[g2][3]));
#pragma unroll
    for (int off = 16; off; off >>= 1)
#pragma unroll
        for (int g2 = 0; g2 < 8; g2++)
            lm[g2] = fmaxf(lm[g2], __shfl_xor_sync(0xffffffffu, lm[g2], off));
    if (lane == 0)
#pragma unroll
        for (int g2 = 0; g2 < 8; g2++) srA[g2][wid] = lm[g2];
    __syncthreads();
    if (tid < 64) {
        float v = srA[tid >> 3][tid & 7];
        v = fmaxf(v, __shfl_xor_sync(0xffffffffu, v, 1));
        v = fmaxf(v, __shfl_xor_sync(0xffffffffu, v, 2));
        v = fmaxf(v, __shfl_xor_sync(0xffffffffu, v, 4));
        if ((tid & 7) == 0) gmaxs[tid >> 3] = v;
    }
    __syncthreads();
    float ls[8], l2[8];
#pragma unroll
    for (int g2 = 0; g2 < 8; g2++) {
        float gm_ = gmaxs[g2];
        float a = 0.f, a2 = 0.f;
#pragma unroll
        for (int j = 0; j < 4; j++) {
            float e = __expf(m[g2][j] - gm_);
            m[g2][j] = e;
            a += e; a2 += e * e;
        }
        ls[g2] = a; l2[g2] = a2;
    }
#pragma unroll
    for (int off = 16; off; off >>= 1)
#pragma unroll
        for (int g2 = 0; g2 < 8; g2++) {
            ls[g2] += __shfl_xor_sync(0xffffffffu, ls[g2], off);
            l2[g2] += __shfl_xor_sync(0xffffffffu, l2[g2], off);
        }
    if (lane == 0)
#pragma unroll
        for (int g2 = 0; g2 < 8; g2++) { srA[g2][wid] = ls[g2]; srB[g2][wid] = l2[g2]; }
    __syncthreads();
    if (tid < 64) {
        float v = srA[tid >> 3][tid & 7];
        float v2 = srB[tid >> 3][tid & 7];
        v  += __shfl_xor_sync(0xffffffffu, v, 1);
        v2 += __shfl_xor_sync(0xffffffffu, v2, 1);
        v  += __shfl_xor_sync(0xffffffffu, v, 2);
        v2 += __shfl_xor_sync(0xffffffffu, v2, 2);
        v  += __shfl_xor_sync(0xffffffffu, v, 4);
        v2 += __shfl_xor_sync(0xffffffffu, v2, 4);
        if ((tid & 7) == 0) {
            float inv = 1.f / v;
            ginv[tid >> 3] = inv;
            gssq[tid >> 3] = v2 * inv * inv;
        }
    }
    __syncthreads();
#pragma unroll
    for (int g2 = 0; g2 < 8; g2++) {
        float inv = ginv[g2];
#pragma unroll
        for (int j = 0; j < 4; j++) {
            int o = tid + j * 256;
            if (o < OQ) {
                long long idx = base0 + (long long)g2 * HS + o;
                float a = m[g2][j] * inv;
                g_attn[idx] = tf32r((a - amean) * aw[idx]);
            }
        }
    }
    if (tid < 8)
        g_pssq[(long long)(b * NH + tid) * NQ + q] = gssq[tid];
}

// ---------------------------------------------------------------------------
// Finalize instance-norm rstd per (b,h)
// ---------------------------------------------------------------------------
__global__ void k_rstd() {
    int z = blockIdx.x;
    int tid = threadIdx.x;
    float s = 0.f;
    for (int i = tid; i < NQ; i += 256) s += g_pssq[(long long)z * NQ + i];
    __shared__ float r1[8];
#pragma unroll
    for (int off = 16; off; off >>= 1)
        s += __shfl_xor_sync(0xffffffffu, s, off);
    if ((tid & 31) == 0) r1[tid >> 5] = s;
    __syncthreads();
    if (tid == 0) {
        float S = 0.f;
        for (int i = 0; i < 8; i++) S += r1[i];
        const float mean = 1.f / OQ;
        float var = S / ((float)NQ * (float)OQ) - mean * mean;
        g_rstd[z] = rsqrtf(var + LEPS);
    }
}

// ---------------------------------------------------------------------------
extern "C" void kernel_launch(void* const* d_in, const int* in_sizes, int n_in,
                              void* d_out, int out_size) {
    const float* x    = (const float*)d_in[0];
    const float* aw   = (const float*)d_in[1];
    const float* q_w  = (const float*)d_in[2];
    const float* k_w  = (const float*)d_in[3];
    const float* v_w  = (const float*)d_in[4];
    const float* sr_w = (const float*)d_in[5];
    const float* sr_b = (const float*)d_in[6];
    const float* ln_g = (const float*)d_in[7];
    const float* ln_b = (const float*)d_in[8];
    const float* tc_w = (const float*)d_in[9];
    const float* tc_b = (const float*)d_in[10];
    const float* pj_b = (const float*)d_in[12];
    float* out = (float*)d_out;

    static bool s_init = false;
    static float *p_xf, *p_xs, *p_q, *p_k, *p_vt, *p_attn, *p_ao, *p_rstd, *p_wr;
    if (!s_init) {
        cudaGetSymbolAddress((void**)&p_xf, g_xf);
        cudaGetSymbolAddress((void**)&p_xs, g_xs);
        cudaGetSymbolAddress((void**)&p_q, g_qb);
        cudaGetSymbolAddress((void**)&p_k, g_kb);
        cudaGetSymbolAddress((void**)&p_vt, g_vt);
        cudaGetSymbolAddress((void**)&p_attn, g_attn);
        cudaGetSymbolAddress((void**)&p_ao, g_ao);
        cudaGetSymbolAddress((void**)&p_rstd, g_rstd);
        cudaGetSymbolAddress((void**)&p_wr, g_wr);
        s_init = true;
    }

    // Stage A: weight rounding + layouts + spatial reduction
    k_wround<<<256, 1024>>>(q_w, k_w, v_w, (const float*)d_in[11]);
    k_transpose<<<dim3(98, 16, 4), dim3(32, 8)>>>(x);
    k_conv<<<BB * CC, 256>>>(x, sr_w, sr_b);
    k_ln<<<BB * OQ, 256>>>(ln_g, ln_b);

    // Stage B: projections (tf32 MMA, cp.async); outputs rounded to tf32
    k_mma2<false, false, true, false><<<dim3(8, 98, 1), 256>>>(
        p_xf, CC, 0, 0, p_wr, CC, 0, 0, p_q, CC, 0, 0,
        BB * NQ, CC, CC, 1.f, nullptr, 0, nullptr);
    k_mma2<false, false, true, false><<<dim3(8, 25, 1), 256>>>(
        p_xs, CC, 0, 0, p_wr + CC*CC, CC, 0, 0, p_k, CC, 0, 0,
        BB * OQ, CC, CC, 1.f, nullptr, 0, nullptr);
    // V: transposed write -> g_vt (B, C, OQ), rounded
    k_mma2<true, false, true, false><<<dim3(8, 25, 1), 256>>>(
        p_xs, CC, 0, 0, p_wr + 2*CC*CC, CC, 0, 0, p_vt, 0, 0, 0,
        BB * OQ, CC, CC, 1.f, nullptr, OQ, nullptr);

    // Stage C: Q-resident QK logits
    k_qk<<<dim3(25, 32), 256>>>(p_q, p_k, p_attn);

    // head-mix + softmax + t=(a-mean)*aw + instnorm stats
    k_mixsoftmax<<<BB * NQ, 256>>>(tc_w, tc_b, aw);
    k_rstd<<<32, 256>>>();

    // Stage D: AV = rstd * (t @ V); output rounded -> g_ao
    k_mma2<false, false, true, true><<<dim3(1, 25, 32), 256>>>(
        p_attn, OQ, (long long)NH * NQ * OQ, (long long)NQ * OQ,
        p_vt, OQ, (long long)CC * OQ, (long long)HD * OQ,
        p_ao, CC, (long long)NQ * CC, HD,
        NQ, HD, OQ, 1.f, nullptr, 0, p_rstd);

    // Stage E: output projection + bias, transposed into (B,C,HW)
    k_mma2<true, true, false, false><<<dim3(8, 98, 1), 256>>>(
        p_ao, CC, 0, 0, p_wr + 3*CC*CC, CC, 0, 0, out, 0, 0, 0,
        BB * NQ, CC, CC, 1.f, pj_b, NQ, nullptr);
}

// round 11
// speedup vs baseline: 1.2766x; 1.2766x over previous
#include <cuda_runtime.h>
#include <cstdint>

#define BB 4
#define CC 512
#define HH 56
#define NQ 3136
#define OQ 784
#define NH 8
#define HD 64
#define LEPS 1e-5f

#define BM 128
#define BN 64
#define BK 16

static __device__ float g_xf[(size_t)BB*NQ*CC];
static __device__ float g_xs[(size_t)BB*OQ*CC];
static __device__ float g_qb[(size_t)BB*NQ*CC];
static __device__ float g_kb[(size_t)BB*OQ*CC];
static __device__ float g_vt[(size_t)BB*CC*OQ];    // V transposed: (B, C, OQ)
static __device__ float g_attn[(size_t)BB*NH*NQ*OQ];   // ~315 MB
static __device__ float g_ao[(size_t)BB*NQ*CC];
static __device__ float g_pssq[(size_t)BB*NH*NQ];
static __device__ float g_rstd[BB*NH];

// ---------------------------------------------------------------------------
// Transpose x (B,C,NQ) -> xf (B,NQ,C)
// ---------------------------------------------------------------------------
__global__ void k_transpose(const float* __restrict__ x) {
    __shared__ float t[32][33];
    int b = blockIdx.z;
    int q0 = blockIdx.x * 32, c0 = blockIdx.y * 32;
    int tx = threadIdx.x, ty = threadIdx.y;
#pragma unroll
    for (int i = 0; i < 32; i += 8)
        t[ty + i][tx] = x[((size_t)b * CC + c0 + ty + i) * NQ + q0 + tx];
    __syncthreads();
#pragma unroll
    for (int i = 0; i < 32; i += 8)
        g_xf[((size_t)b * NQ + q0 + ty + i) * CC + c0 + tx] = t[tx][ty + i];
}

// ---------------------------------------------------------------------------
// Depthwise 3x3 stride-2 pad-1 conv + bias -> g_xs (B,OQ,C)
// ---------------------------------------------------------------------------
__global__ void k_conv(const float* __restrict__ x, const float* __restrict__ w,
                       const float* __restrict__ bias) {
    int bc = blockIdx.x;
    int b = bc >> 9;
    int c = bc & 511;
    __shared__ float sx[HH * HH];
    const float* xp = x + ((size_t)b * CC + c) * NQ;
    for (int i = threadIdx.x; i < HH * HH; i += 256) sx[i] = xp[i];
    float w0 = w[c*9+0], w1 = w[c*9+1], w2 = w[c*9+2];
    float w3 = w[c*9+3], w4 = w[c*9+4], w5 = w[c*9+5];
    float w6 = w[c*9+6], w7 = w[c*9+7], w8 = w[c*9+8];
    float bi = bias[c];
    __syncthreads();
    for (int o = threadIdx.x; o < OQ; o += 256) {
        int oy = o / 28, ox = o - oy * 28;
        int y0 = oy * 2 - 1, x0 = ox * 2 - 1;
        float s = bi;
        if (y0 >= 0) {
            const float* r = &sx[y0 * HH];
            if (x0 >= 0) s += r[x0] * w0;
            s += r[x0 + 1] * w1 + r[x0 + 2] * w2;
        }
        {
            const float* r = &sx[(y0 + 1) * HH];
            if (x0 >= 0) s += r[x0] * w3;
            s += r[x0 + 1] * w4 + r[x0 + 2] * w5;
        }
        {
            const float* r = &sx[(y0 + 2) * HH];
            if (x0 >= 0) s += r[x0] * w6;
            s += r[x0 + 1] * w7 + r[x0 + 2] * w8;
        }
        g_xs[((size_t)b * OQ + o) * CC + c] = s;
    }
}

// ---------------------------------------------------------------------------
// LayerNorm over C=512 per (b,o), in place on g_xs
// ---------------------------------------------------------------------------
__global__ void k_ln(const float* __restrict__ gam, const float* __restrict__ bet) {
    int row = blockIdx.x;
    float* p = g_xs + (size_t)row * CC;
    int tid = threadIdx.x;
    float v0 = p[tid], v1 = p[tid + 256];
    float s = v0 + v1, sq = v0 * v0 + v1 * v1;
    __shared__ float r1[8], r2[8];
    __shared__ float s_m, s_r;
#pragma unroll
    for (int off = 16; off; off >>= 1) {
        s  += __shfl_xor_sync(0xffffffffu, s, off);
        sq += __shfl_xor_sync(0xffffffffu, sq, off);
    }
    if ((tid & 31) == 0) { r1[tid >> 5] = s; r2[tid >> 5] = sq; }
    __syncthreads();
    if (tid == 0) {
        float S = 0.f, Q = 0.f;
        for (int i = 0; i < 8; i++) { S += r1[i]; Q += r2[i]; }
        float mean = S * (1.f / CC);
        float var = Q * (1.f / CC) - mean * mean;
        s_m = mean;
        s_r = rsqrtf(var + LEPS);
    }
    __syncthreads();
    float mean = s_m, rs = s_r;
    p[tid]       = (v0 - mean) * rs * gam[tid]       + bet[tid];
    p[tid + 256] = (v1 - mean) * rs * gam[tid + 256] + bet[tid + 256];
}

// ---------------------------------------------------------------------------
__device__ __forceinline__ float tf32r(float x) {
    uint32_t u;
    asm("cvt.rna.tf32.f32 %0, %1;" : "=r"(u) : "f"(x));
    return __uint_as_float(u);
}
__device__ __forceinline__ float4 tf32r4(float4 v) {
    v.x = tf32r(v.x); v.y = tf32r(v.y); v.z = tf32r(v.z); v.w = tf32r(v.w);
    return v;
}

// ---------------------------------------------------------------------------
// TF32 tensor-core NT GEMM: C[m,n] = alpha * sum_k A[m,k]*W[n,k] (+bias)
// BM=128, BN=64, BK=16; 8 warps (4 M x 2 N), 32x32 warptiles of m16n8k8.
// __launch_bounds__(256,3): cap regs at 85 so 3 CTAs/SM fit (was 88 -> 2).
// ---------------------------------------------------------------------------
template <bool TRANS_OUT, bool HAS_BIAS, bool FUSE_A>
__global__ void __launch_bounds__(256, 3)
k_mma(const float* __restrict__ A, int lda, long long sAb, long long sAh,
      const float* __restrict__ W, int ldw, long long sWb, long long sWh,
      float* __restrict__ Cp, int ldc, long long sCb, long long sCh,
      int M, int N, int K, float alpha, const float* __restrict__ bias,
      int trows, const float* __restrict__ A2, const float* __restrict__ rstdp) {
    __shared__ float4 As4[2][4 * BM];   // 512 float4 per buffer
    __shared__ float4 Bs4[2][4 * BN];   // 256 float4 per buffer

    int bz = blockIdx.z;
    long long offA = (long long)(bz >> 3) * sAb + (long long)(bz & 7) * sAh;
    A += offA;
    W += (long long)(bz >> 3) * sWb + (long long)(bz & 7) * sWh;
    Cp += (long long)(bz >> 3) * sCb + (long long)(bz & 7) * sCh;
    float rs = 0.f;
    const float amean = 1.f / OQ;
    if (FUSE_A) { A2 += offA; rs = rstdp[bz]; }

    int m0 = blockIdx.y * BM, n0 = blockIdx.x * BN;
    int tid = threadIdx.x;
    int lane = tid & 31, warp = tid >> 5;
    int wm = (warp & 3) * 32, wn = (warp >> 2) * 32;
    int gid = lane >> 2, tig = lane & 3;
    int lk4 = tid & 3, lrow = tid >> 2;

    int gmA0 = min(m0 + lrow, M - 1);
    int gmA1 = min(m0 + lrow + 64, M - 1);
    int gnB  = min(n0 + lrow, N - 1);
    const float* pAg0 = A + (size_t)gmA0 * lda + lk4 * 4;
    const float* pAg1 = A + (size_t)gmA1 * lda + lk4 * 4;
    const float* pWg  = W + (size_t)gnB * ldw + lk4 * 4;
    const float* pA2g0 = nullptr; const float* pA2g1 = nullptr;
    if (FUSE_A) {
        pA2g0 = A2 + (size_t)gmA0 * lda + lk4 * 4;
        pA2g1 = A2 + (size_t)gmA1 * lda + lk4 * 4;
    }

    float4* stA = &As4[0][lk4 * BM + (lrow ^ (lk4 << 1))];
    float4* stB = &Bs4[0][lk4 * BN + (lrow ^ (lk4 << 1))];

    const float* fA[4];
    const float* fB[4];
#pragma unroll
    for (int k4 = 0; k4 < 4; k4++) {
        int gx = gid ^ (k4 << 1);
        fA[k4] = (const float*)As4 + k4 * (BM * 4) + (wm + gx) * 4 + tig;
        fB[k4] = (const float*)Bs4 + k4 * (BN * 4) + (wn + gx) * 4 + tig;
    }

    float acc[2][4][4];
#pragma unroll
    for (int i = 0; i < 2; i++)
#pragma unroll
        for (int j = 0; j < 4; j++)
#pragma unroll
            for (int l = 0; l < 4; l++) acc[i][j][l] = 0.f;

    float4 ra0, ra1, rb;

#define LOAD_TILE()                                                            \
    {                                                                          \
        ra0 = *(const float4*)pAg0;                                            \
        ra1 = *(const float4*)pAg1;                                            \
        rb  = *(const float4*)pWg;                                             \
        if (FUSE_A) {                                                          \
            float4 w0 = *(const float4*)pA2g0;                                 \
            float4 w1 = *(const float4*)pA2g1;                                 \
            ra0.x = (ra0.x - amean) * rs * w0.x;                               \
            ra0.y = (ra0.y - amean) * rs * w0.y;                               \
            ra0.z = (ra0.z - amean) * rs * w0.z;                               \
            ra0.w = (ra0.w - amean) * rs * w0.w;                               \
            ra1.x = (ra1.x - amean) * rs * w1.x;                               \
            ra1.y = (ra1.y - amean) * rs * w1.y;                               \
            ra1.z = (ra1.z - amean) * rs * w1.z;                               \
            ra1.w = (ra1.w - amean) * rs * w1.w;                               \
            pA2g0 += BK; pA2g1 += BK;                                          \
        }                                                                      \
        pAg0 += BK; pAg1 += BK; pWg += BK;                                     \
    }

#define STORE_TILE()                                                           \
    {                                                                          \
        stA[0]  = tf32r4(ra0);                                                 \
        stA[64] = tf32r4(ra1);                                                 \
        stB[0]  = tf32r4(rb);                                                  \
    }

#define COMPUTE()                                                              \
    {                                                                          \
        _Pragma("unroll")                                                      \
        for (int ks = 0; ks < 2; ks++) {                                       \
            const float* a0p = fA[2 * ks];                                     \
            const float* a1p = fA[2 * ks + 1];                                 \
            const float* b0p = fB[2 * ks];                                     \
            const float* b1p = fB[2 * ks + 1];                                 \
            uint32_t af[2][4], bf[4][2];                                       \
            _Pragma("unroll")                                                  \
            for (int mi = 0; mi < 2; mi++) {                                   \
                af[mi][0] = __float_as_uint(a0p[mi * 64]);                     \
                af[mi][1] = __float_as_uint(a0p[mi * 64 + 32]);                \
                af[mi][2] = __float_as_uint(a1p[mi * 64]);                     \
                af[mi][3] = __float_as_uint(a1p[mi * 64 + 32]);                \
            }                                                                  \
            _Pragma("unroll")                                                  \
            for (int ni = 0; ni < 4; ni++) {                                   \
                bf[ni][0] = __float_as_uint(b0p[ni * 32]);                     \
                bf[ni][1] = __float_as_uint(b1p[ni * 32]);                     \
            }                                                                  \
            _Pragma("unroll")                                                  \
            for (int mi = 0; mi < 2; mi++)                                     \
            _Pragma("unroll")                                                  \
            for (int ni = 0; ni < 4; ni++) {                                   \
                asm volatile(                                                  \
                    "mma.sync.aligned.m16n8k8.row.col.f32.tf32.tf32.f32 "      \
                    "{%0,%1,%2,%3}, {%4,%5,%6,%7}, {%8,%9}, {%0,%1,%2,%3};"    \
                    : "+f"(acc[mi][ni][0]), "+f"(acc[mi][ni][1]),              \
                      "+f"(acc[mi][ni][2]), "+f"(acc[mi][ni][3])               \
                    : "r"(af[mi][0]), "r"(af[mi][1]),                          \
                      "r"(af[mi][2]), "r"(af[mi][3]),                          \
                      "r"(bf[ni][0]), "r"(bf[ni][1]));                         \
            }                                                                  \
        }                                                                      \
    }

    LOAD_TILE();
    STORE_TILE();
    __syncthreads();

    int dSA = 512, dSB = 256;
    int dFA = 2048, dFB = 1024;
    int nkb = K / BK;
    for (int kb = 0; kb < nkb; kb++) {
        bool more = (kb + 1 < nkb);
        if (more) LOAD_TILE();
        COMPUTE();
        if (more) {
            stA += dSA; stB += dSB; dSA = -dSA; dSB = -dSB;
            STORE_TILE();
#pragma unroll
            for (int k4 = 0; k4 < 4; k4++) { fA[k4] += dFA; fB[k4] += dFB; }
            dFA = -dFA; dFB = -dFB;
            __syncthreads();
        }
    }

#pragma unroll
    for (int mi = 0; mi < 2; mi++)
#pragma unroll
    for (int ni = 0; ni < 4; ni++) {
        int r0 = m0 + wm + mi * 16 + gid;
        int c0 = n0 + wn + ni * 8 + tig * 2;
#pragma unroll
        for (int half = 0; half < 2; half++) {
            int r = r0 + half * 8;
            if (r >= M) continue;
#pragma unroll
            for (int cc2 = 0; cc2 < 2; cc2++) {
                int c = c0 + cc2;
                if (c >= N) continue;
                float vv = acc[mi][ni][half * 2 + cc2] * alpha;
                if (HAS_BIAS) vv += bias[c];
                if (TRANS_OUT) {
                    int bidx = r / trows, q = r - bidx * trows;
                    Cp[((long long)bidx * N + c) * trows + q] = vv;
                } else {
                    Cp[(long long)r * ldc + c] = vv;
                }
            }
        }
    }
#undef LOAD_TILE
#undef STORE_TILE
#undef COMPUTE
}

// ---------------------------------------------------------------------------
// Specialized QK logits kernel. Block = (b,h, 128 q-rows). Q-tile (128x64,
// full K) resident in smem; stream K-tiles of 64 o-rows (double-buffered via
// registers), full K=64 accumulation per chunk, write 128x64 logits chunk.
// ---------------------------------------------------------------------------
#define NCH ((OQ + 63) / 64)   // 13 chunks (last partial: 16 cols)

__global__ void __launch_bounds__(256, 2)
k_qk(const float* __restrict__ Qm, const float* __restrict__ Km,
     float* __restrict__ attn) {
    __shared__ float4 Aq[16 * 128];     // 32 KB
    __shared__ float4 Bk[2][16 * 64];   // 2 x 16 KB

    int z = blockIdx.y;
    int b = z >> 3, h = z & 7;
    int q0 = blockIdx.x * 128;
    const float* Qp = Qm + (size_t)b * NQ * CC + h * HD;
    const float* Kp = Km + (size_t)b * OQ * CC + h * HD;
    float* Op = attn + (size_t)z * NQ * OQ;

    int tid = threadIdx.x;
    int lane = tid & 31, warp = tid >> 5;
    int wm = (warp & 3) * 32, wn = (warp >> 2) * 32;
    int gid = lane >> 2, tig = lane & 3;
    int lk4 = tid & 3, lrow = tid >> 2;

#pragma unroll
    for (int kt = 0; kt < 4; kt++)
#pragma unroll
        for (int it = 0; it < 2; it++) {
            int r = lrow + it * 64;
            int gm = min(q0 + r, NQ - 1);
            float4 v = *(const float4*)(Qp + (size_t)gm * CC + kt * 16 + lk4 * 4);
            Aq[(kt * 4 + lk4) * 128 + (r ^ (lk4 << 1))] = tf32r4(v);
        }

    float4 rbv[4];
#define LOADB(J)                                                               \
    {                                                                          \
        int go = min((J) * 64 + lrow, OQ - 1);                                 \
        const float* src = Kp + (size_t)go * CC + lk4 * 4;                     \
        _Pragma("unroll")                                                      \
        for (int kt = 0; kt < 4; kt++) rbv[kt] = *(const float4*)(src + kt * 16); \
    }
#define STOREB(BUF)                                                            \
    {                                                                          \
        _Pragma("unroll")                                                      \
        for (int kt = 0; kt < 4; kt++)                                         \
            Bk[BUF][(kt * 4 + lk4) * 64 + (lrow ^ (lk4 << 1))] = tf32r4(rbv[kt]); \
    }

    LOADB(0);
    STOREB(0);
    __syncthreads();

    const float* Af = (const float*)Aq;
    for (int j = 0; j < NCH; j++) {
        int buf = j & 1;
        bool more = (j + 1 < NCH);
        if (more) LOADB(j + 1);

        float acc[2][4][4];
#pragma unroll
        for (int i = 0; i < 2; i++)
#pragma unroll
            for (int jj = 0; jj < 4; jj++)
#pragma unroll
                for (int l = 0; l < 4; l++) acc[i][jj][l] = 0.f;

        const float* Bf = (const float*)Bk[buf];
#pragma unroll
        for (int ks = 0; ks < 8; ks++) {
            const int k4a = 2 * ks, k4b = 2 * ks + 1;
            const int ca = (k4a & 3) << 1, cb = (k4b & 3) << 1;
            uint32_t af[2][4], bf[4][2];
#pragma unroll
            for (int mi = 0; mi < 2; mi++) {
                int ra = (wm + mi * 16 + gid) ^ ca;
                int rb2 = (wm + mi * 16 + gid) ^ cb;
                af[mi][0] = __float_as_uint(Af[(k4a * 128 + ra) * 4 + tig]);
                af[mi][1] = __float_as_uint(Af[(k4a * 128 + ra + 8) * 4 + tig]);
                af[mi][2] = __float_as_uint(Af[(k4b * 128 + rb2) * 4 + tig]);
                af[mi][3] = __float_as_uint(Af[(k4b * 128 + rb2 + 8) * 4 + tig]);
            }
#pragma unroll
            for (int ni = 0; ni < 4; ni++) {
                int na = (wn + ni * 8 + gid) ^ ca;
                int nb = (wn + ni * 8 + gid) ^ cb;
                bf[ni][0] = __float_as_uint(Bf[(k4a * 64 + na) * 4 + tig]);
                bf[ni][1] = __float_as_uint(Bf[(k4b * 64 + nb) * 4 + tig]);
            }
#pragma unroll
            for (int mi = 0; mi < 2; mi++)
#pragma unroll
            for (int ni = 0; ni < 4; ni++) {
                asm volatile(
                    "mma.sync.aligned.m16n8k8.row.col.f32.tf32.tf32.f32 "
                    "{%0,%1,%2,%3}, {%4,%5,%6,%7}, {%8,%9}, {%0,%1,%2,%3};"
                    : "+f"(acc[mi][ni][0]), "+f"(acc[mi][ni][1]),
                      "+f"(acc[mi][ni][2]), "+f"(acc[mi][ni][3])
                    : "r"(af[mi][0]), "r"(af[mi][1]),
                      "r"(af[mi][2]), "r"(af[mi][3]),
                      "r"(bf[ni][0]), "r"(bf[ni][1]));
            }
        }

        int o0 = j * 64;
#pragma unroll
        for (int mi = 0; mi < 2; mi++)
#pragma unroll
        for (int ni = 0; ni < 4; ni++) {
            int r0 = q0 + wm + mi * 16 + gid;
            int c0 = o0 + wn + ni * 8 + tig * 2;
#pragma unroll
            for (int half = 0; half < 2; half++) {
                int r = r0 + half * 8;
                if (r >= NQ) continue;
#pragma unroll
                for (int cc2 = 0; cc2 < 2; cc2++) {
                    int c = c0 + cc2;
                    if (c >= OQ) continue;
                    Op[(size_t)r * OQ + c] = acc[mi][ni][half * 2 + cc2] * 0.125f;
                }
            }
        }

        if (more) {
            STOREB(buf ^ 1);
            __syncthreads();
        }
    }
#undef LOADB
#undef STOREB
}

// ---------------------------------------------------------------------------
// Fused head-mix (tc_w/tc_b) + softmax over OQ, in place on g_attn.
// ---------------------------------------------------------------------------
__global__ void __launch_bounds__(256)
k_mixsoftmax(const float* __restrict__ tcw, const float* __restrict__ tcb) {
    int bq = blockIdx.x;
    int b = bq / NQ;
    int q = bq - b * NQ;
    int tid = threadIdx.x;
    int lane = tid & 31, wid = tid >> 5;
    __shared__ float s_w[64];
    __shared__ float s_b[8];
    __shared__ float srA[8][8];
    __shared__ float srB[8][8];
    __shared__ float gmaxs[8];
    __shared__ float ginv[8];
    __shared__ float gssq[8];
    if (tid < 64) s_w[tid] = tcw[tid];
    if (tid < 8)  s_b[tid] = tcb[tid];
    __syncthreads();
    const long long HS = (long long)NQ * OQ;
    long long base0 = (long long)b * NH * HS + (long long)q * OQ;
    float m[8][4];
#pragma unroll
    for (int j = 0; j < 4; j++) {
        int o = tid + j * 256;
        bool valid = o < OQ;
        float lh[8];
#pragma unroll
        for (int h = 0; h < 8; h++)
            lh[h] = valid ? g_attn[base0 + (long long)h * HS + o] : 0.f;
#pragma unroll
        for (int g2 = 0; g2 < 8; g2++) {
            float s = s_b[g2];
#pragma unroll
            for (int h = 0; h < 8; h++) s += s_w[g2 * 8 + h] * lh[h];
            m[g2][j] = valid ? s : -1e30f;
        }
    }
    float lm[8];
#pragma unroll
    for (int g2 = 0; g2 < 8; g2++)
        lm[g2] = fmaxf(fmaxf(m[g2][0], m[g2][1]), fmaxf(m[g2][2], m[g2][3]));
#pragma unroll
    for (int off = 16; off; off >>= 1)
#pragma unroll
        for (int g2 = 0; g2 < 8; g2++)
            lm[g2] = fmaxf(lm[g2], __shfl_xor_sync(0xffffffffu, lm[g2], off));
    if (lane == 0)
#pragma unroll
        for (int g2 = 0; g2 < 8; g2++) srA[g2][wid] = lm[g2];
    __syncthreads();
    if (tid < 64) {
        float v = srA[tid >> 3][tid & 7];
        v = fmaxf(v, __shfl_xor_sync(0xffffffffu, v, 1));
        v = fmaxf(v, __shfl_xor_sync(0xffffffffu, v, 2));
        v = fmaxf(v, __shfl_xor_sync(0xffffffffu, v, 4));
        if ((tid & 7) == 0) gmaxs[tid >> 3] = v;
    }
    __syncthreads();
    float ls[8], l2[8];
#pragma unroll
    for (int g2 = 0; g2 < 8; g2++) {
        float gm_ = gmaxs[g2];
        float a = 0.f, a2 = 0.f;
#pragma unroll
        for (int j = 0; j < 4; j++) {
            float e = __expf(m[g2][j] - gm_);
            m[g2][j] = e;
            a += e; a2 += e * e;
        }
        ls[g2] = a; l2[g2] = a2;
    }
#pragma unroll
    for (int off = 16; off; off >>= 1)
#pragma unroll
        for (int g2 = 0; g2 < 8; g2++) {
            ls[g2] += __shfl_xor_sync(0xffffffffu, ls[g2], off);
            l2[g2] += __shfl_xor_sync(0xffffffffu, l2[g2], off);
        }
    if (lane == 0)
#pragma unroll
        for (int g2 = 0; g2 < 8; g2++) { srA[g2][wid] = ls[g2]; srB[g2][wid] = l2[g2]; }
    __syncthreads();
    if (tid < 64) {
        float v = srA[tid >> 3][tid & 7];
        float v2 = srB[tid >> 3][tid & 7];
        v  += __shfl_xor_sync(0xffffffffu, v, 1);
        v2 += __shfl_xor_sync(0xffffffffu, v2, 1);
        v  += __shfl_xor_sync(0xffffffffu, v, 2);
        v2 += __shfl_xor_sync(0xffffffffu, v2, 2);
        v  += __shfl_xor_sync(0xffffffffu, v, 4);
        v2 += __shfl_xor_sync(0xffffffffu, v2, 4);
        if ((tid & 7) == 0) {
            float inv = 1.f / v;
            ginv[tid >> 3] = inv;
            gssq[tid >> 3] = v2 * inv * inv;
        }
    }
    __syncthreads();
#pragma unroll
    for (int g2 = 0; g2 < 8; g2++) {
        float inv = ginv[g2];
#pragma unroll
        for (int j = 0; j < 4; j++) {
            int o = tid + j * 256;
            if (o < OQ)
                g_attn[base0 + (long long)g2 * HS + o] = m[g2][j] * inv;
        }
    }
    if (tid < 8)
        g_pssq[(long long)(b * NH + tid) * NQ + q] = gssq[tid];
}

// ---------------------------------------------------------------------------
// Finalize instance-norm rstd per (b,h)
// ---------------------------------------------------------------------------
__global__ void k_rstd() {
    int z = blockIdx.x;
    int tid = threadIdx.x;
    float s = 0.f;
    for (int i = tid; i < NQ; i += 256) s += g_pssq[(long long)z * NQ + i];
    __shared__ float r1[8];
#pragma unroll
    for (int off = 16; off; off >>= 1)
        s += __shfl_xor_sync(0xffffffffu, s, off);
    if ((tid & 31) == 0) r1[tid >> 5] = s;
    __syncthreads();
    if (tid == 0) {
        float S = 0.f;
        for (int i = 0; i < 8; i++) S += r1[i];
        const float mean = 1.f / OQ;
        float var = S / ((float)NQ * (float)OQ) - mean * mean;
        g_rstd[z] = rsqrtf(var + LEPS);
    }
}

// ---------------------------------------------------------------------------
extern "C" void kernel_launch(void* const* d_in, const int* in_sizes, int n_in,
                              void* d_out, int out_size) {
    const float* x    = (const float*)d_in[0];
    const float* aw   = (const float*)d_in[1];
    const float* q_w  = (const float*)d_in[2];
    const float* k_w  = (const float*)d_in[3];
    const float* v_w  = (const float*)d_in[4];
    const float* sr_w = (const float*)d_in[5];
    const float* sr_b = (const float*)d_in[6];
    const float* ln_g = (const float*)d_in[7];
    const float* ln_b = (const float*)d_in[8];
    const float* tc_w = (const float*)d_in[9];
    const float* tc_b = (const float*)d_in[10];
    const float* pj_w = (const float*)d_in[11];
    const float* pj_b = (const float*)d_in[12];
    float* out = (float*)d_out;

    static bool s_init = false;
    static float *p_xf, *p_xs, *p_q, *p_k, *p_vt, *p_attn, *p_ao, *p_rstd;
    if (!s_init) {
        cudaGetSymbolAddress((void**)&p_xf, g_xf);
        cudaGetSymbolAddress((void**)&p_xs, g_xs);
        cudaGetSymbolAddress((void**)&p_q, g_qb);
        cudaGetSymbolAddress((void**)&p_k, g_kb);
        cudaGetSymbolAddress((void**)&p_vt, g_vt);
        cudaGetSymbolAddress((void**)&p_attn, g_attn);
        cudaGetSymbolAddress((void**)&p_ao, g_ao);
        cudaGetSymbolAddress((void**)&p_rstd, g_rstd);
        s_init = true;
    }

    // Stage A: layouts + spatial reduction
    k_transpose<<<dim3(98, 16, 4), dim3(32, 8)>>>(x);
    k_conv<<<BB * CC, 256>>>(x, sr_w, sr_b);
    k_ln<<<BB * OQ, 256>>>(ln_g, ln_b);

    // Stage B: projections (tf32 tensor cores)
    k_mma<false, false, false><<<dim3(8, 98, 1), 256>>>(
        p_xf, CC, 0, 0, q_w, CC, 0, 0, p_q, CC, 0, 0,
        BB * NQ, CC, CC, 1.f, nullptr, 0, nullptr, nullptr);
    k_mma<false, false, false><<<dim3(8, 25, 1), 256>>>(
        p_xs, CC, 0, 0, k_w, CC, 0, 0, p_k, CC, 0, 0,
        BB * OQ, CC, CC, 1.f, nullptr, 0, nullptr, nullptr);
    // V: transposed write -> g_vt (B, C, OQ)
    k_mma<true, false, false><<<dim3(8, 25, 1), 256>>>(
        p_xs, CC, 0, 0, v_w, CC, 0, 0, p_vt, 0, 0, 0,
        BB * OQ, CC, CC, 1.f, nullptr, OQ, nullptr, nullptr);

    // Stage C: specialized Q-resident QK logits kernel
    k_qk<<<dim3(25, 32), 256>>>(p_q, p_k, p_attn);

    // head-mix + softmax + instnorm stats
    k_mixsoftmax<<<BB * NQ, 256>>>(tc_w, tc_b);
    k_rstd<<<32, 256>>>();

    // Stage D: fused (instnorm * attn_weights) @ V  (V from g_vt, K-contig)
    k_mma<false, false, true><<<dim3(1, 25, 32), 256>>>(
        p_attn, OQ, (long long)NH * NQ * OQ, (long long)NQ * OQ,
        p_vt, OQ, (long long)CC * OQ, (long long)HD * OQ,
        p_ao, CC, (long long)NQ * CC, HD,
        NQ, HD, OQ, 1.f, nullptr, 0, aw, p_rstd);

    // Stage E: output projection + bias, written transposed into (B,C,HW)
    k_mma<true, true, false><<<dim3(8, 98, 1), 256>>>(
        p_ao, CC, 0, 0, pj_w, CC, 0, 0, out, 0, 0, 0,
        BB * NQ, CC, CC, 1.f, pj_b, NQ, nullptr, nullptr);
}

// round 16
// speedup vs baseline: 1.3276x; 1.0399x over previous
#include <cuda_runtime.h>
#include <cuda_fp16.h>
#include <cstdint>

#define BB 4
#define CC 512
#define HH 56
#define NQ 3136
#define OQ 784
#define NH 8
#define HD 64
#define LEPS 1e-5f

#define BM 128
#define BN 64
#define BK 16

static __device__ float g_xf[(size_t)BB*NQ*CC];
static __device__ float g_xs[(size_t)BB*OQ*CC];
static __device__ float g_qb[(size_t)BB*NQ*CC];
static __device__ float g_kb[(size_t)BB*OQ*CC];
static __device__ float g_vt[(size_t)BB*CC*OQ];    // V transposed: (B, C, OQ)
static __device__ float g_attn[(size_t)BB*NH*NQ*OQ];   // ~315 MB
static __device__ float g_ao[(size_t)BB*NQ*CC];
static __device__ float g_pssq[(size_t)BB*NH*NQ];
static __device__ float g_rstd[BB*NH];

// ---------------------------------------------------------------------------
__device__ __forceinline__ uint32_t f2h2(float a, float b) {
    __half2 h = __floats2half2_rn(a, b);   // lo = a, hi = b
    return *reinterpret_cast<uint32_t*>(&h);
}

#define HMMA16816(d, a, b)                                                     \
    asm volatile(                                                              \
        "mma.sync.aligned.m16n8k16.row.col.f32.f16.f16.f32 "                   \
        "{%0,%1,%2,%3}, {%4,%5,%6,%7}, {%8,%9}, {%0,%1,%2,%3};"                \
        : "+f"((d)[0]), "+f"((d)[1]), "+f"((d)[2]), "+f"((d)[3])               \
        : "r"((a)[0]), "r"((a)[1]), "r"((a)[2]), "r"((a)[3]),                  \
          "r"((b)[0]), "r"((b)[1]))

// ---------------------------------------------------------------------------
// Transpose x (B,C,NQ) -> xf (B,NQ,C)
// ---------------------------------------------------------------------------
__global__ void k_transpose(const float* __restrict__ x) {
    __shared__ float t[32][33];
    int b = blockIdx.z;
    int q0 = blockIdx.x * 32, c0 = blockIdx.y * 32;
    int tx = threadIdx.x, ty = threadIdx.y;
#pragma unroll
    for (int i = 0; i < 32; i += 8)
        t[ty + i][tx] = x[((size_t)b * CC + c0 + ty + i) * NQ + q0 + tx];
    __syncthreads();
#pragma unroll
    for (int i = 0; i < 32; i += 8)
        g_xf[((size_t)b * NQ + q0 + ty + i) * CC + c0 + tx] = t[tx][ty + i];
}

// ---------------------------------------------------------------------------
// Depthwise 3x3 stride-2 pad-1 conv + bias -> g_xs (B,OQ,C)
// ---------------------------------------------------------------------------
__global__ void k_conv(const float* __restrict__ x, const float* __restrict__ w,
                       const float* __restrict__ bias) {
    int bc = blockIdx.x;
    int b = bc >> 9;
    int c = bc & 511;
    __shared__ float sx[HH * HH];
    const float* xp = x + ((size_t)b * CC + c) * NQ;
    for (int i = threadIdx.x; i < HH * HH; i += 256) sx[i] = xp[i];
    float w0 = w[c*9+0], w1 = w[c*9+1], w2 = w[c*9+2];
    float w3 = w[c*9+3], w4 = w[c*9+4], w5 = w[c*9+5];
    float w6 = w[c*9+6], w7 = w[c*9+7], w8 = w[c*9+8];
    float bi = bias[c];
    __syncthreads();
    for (int o = threadIdx.x; o < OQ; o += 256) {
        int oy = o / 28, ox = o - oy * 28;
        int y0 = oy * 2 - 1, x0 = ox * 2 - 1;
        float s = bi;
        if (y0 >= 0) {
            const float* r = &sx[y0 * HH];
            if (x0 >= 0) s += r[x0] * w0;
            s += r[x0 + 1] * w1 + r[x0 + 2] * w2;
        }
        {
            const float* r = &sx[(y0 + 1) * HH];
            if (x0 >= 0) s += r[x0] * w3;
            s += r[x0 + 1] * w4 + r[x0 + 2] * w5;
        }
        {
            const float* r = &sx[(y0 + 2) * HH];
            if (x0 >= 0) s += r[x0] * w6;
            s += r[x0 + 1] * w7 + r[x0 + 2] * w8;
        }
        g_xs[((size_t)b * OQ + o) * CC + c] = s;
    }
}

// ---------------------------------------------------------------------------
// LayerNorm over C=512 per (b,o), in place on g_xs
// ---------------------------------------------------------------------------
__global__ void k_ln(const float* __restrict__ gam, const float* __restrict__ bet) {
    int row = blockIdx.x;
    float* p = g_xs + (size_t)row * CC;
    int tid = threadIdx.x;
    float v0 = p[tid], v1 = p[tid + 256];
    float s = v0 + v1, sq = v0 * v0 + v1 * v1;
    __shared__ float r1[8], r2[8];
    __shared__ float s_m, s_r;
#pragma unroll
    for (int off = 16; off; off >>= 1) {
        s  += __shfl_xor_sync(0xffffffffu, s, off);
        sq += __shfl_xor_sync(0xffffffffu, sq, off);
    }
    if ((tid & 31) == 0) { r1[tid >> 5] = s; r2[tid >> 5] = sq; }
    __syncthreads();
    if (tid == 0) {
        float S = 0.f, Q = 0.f;
        for (int i = 0; i < 8; i++) { S += r1[i]; Q += r2[i]; }
        float mean = S * (1.f / CC);
        float var = Q * (1.f / CC) - mean * mean;
        s_m = mean;
        s_r = rsqrtf(var + LEPS);
    }
    __syncthreads();
    float mean = s_m, rs = s_r;
    p[tid]       = (v0 - mean) * rs * gam[tid]       + bet[tid];
    p[tid + 256] = (v1 - mean) * rs * gam[tid + 256] + bet[tid + 256];
}

// ---------------------------------------------------------------------------
// FP16 tensor-core NT GEMM: C[m,n] = alpha * sum_k A[m,k]*W[n,k] (+bias)
// BM=128, BN=64, BK=16; 8 warps (4 M x 2 N), 32x32 warptiles of m16n8k16.
// Smem: k2-major half2 planes, swizzle row^((k2&3)<<3); fragments conflict-
// free; all addresses base+immediate. Operands rounded to fp16 at STS.
// ---------------------------------------------------------------------------
template <bool TRANS_OUT, bool HAS_BIAS, bool FUSE_A>
__global__ void __launch_bounds__(256, 3)
k_mma(const float* __restrict__ A, int lda, long long sAb, long long sAh,
      const float* __restrict__ W, int ldw, long long sWb, long long sWh,
      float* __restrict__ Cp, int ldc, long long sCb, long long sCh,
      int M, int N, int K, float alpha, const float* __restrict__ bias,
      int trows, const float* __restrict__ A2, const float* __restrict__ rstdp) {
    __shared__ uint32_t AsW[2][8 * BM];   // 4 KB per buffer
    __shared__ uint32_t BsW[2][8 * BN];   // 2 KB per buffer

    int bz = blockIdx.z;
    long long offA = (long long)(bz >> 3) * sAb + (long long)(bz & 7) * sAh;
    A += offA;
    W += (long long)(bz >> 3) * sWb + (long long)(bz & 7) * sWh;
    Cp += (long long)(bz >> 3) * sCb + (long long)(bz & 7) * sCh;
    float rs = 0.f;
    const float amean = 1.f / OQ;
    if (FUSE_A) { A2 += offA; rs = rstdp[bz]; }

    int m0 = blockIdx.y * BM, n0 = blockIdx.x * BN;
    int tid = threadIdx.x;
    int lane = tid & 31, warp = tid >> 5;
    int wm = (warp & 3) * 32, wn = (warp >> 2) * 32;
    int gid = lane >> 2, tig = lane & 3;

    // loaders: A 1 row / 2 threads; B 1 row / 4 threads
    int rA = tid >> 1, kh = tid & 1;
    int rB = tid >> 2, kq = tid & 3;
    int gmA = min(m0 + rA, M - 1);
    int gnB = min(n0 + rB, N - 1);
    const float* pAg = A + (size_t)gmA * lda + kh * 8;
    const float* pWg = W + (size_t)gnB * ldw + kq * 4;
    const float* pA2g = nullptr;
    if (FUSE_A) pA2g = A2 + (size_t)gmA * lda + kh * 8;

    uint32_t iSA[4], iSB[2];
#pragma unroll
    for (int j = 0; j < 4; j++)
        iSA[j] = (kh * 4 + j) * BM + (rA ^ (j << 3));
#pragma unroll
    for (int i = 0; i < 2; i++) {
        int k2 = kq * 2 + i;
        iSB[i] = k2 * BN + (rB ^ ((k2 & 3) << 3));
    }

    uint32_t iA0[2], iA1[2], iB0[4];
#pragma unroll
    for (int mi = 0; mi < 2; mi++) {
        iA0[mi] = tig * BM + ((wm + mi * 16 + gid) ^ (tig << 3));
        iA1[mi] = iA0[mi] ^ 8;
    }
#pragma unroll
    for (int ni = 0; ni < 4; ni++)
        iB0[ni] = tig * BN + ((wn + ni * 8 + gid) ^ (tig << 3));

    float acc[2][4][4];
#pragma unroll
    for (int i = 0; i < 2; i++)
#pragma unroll
        for (int j = 0; j < 4; j++)
#pragma unroll
            for (int l = 0; l < 4; l++) acc[i][j][l] = 0.f;

    float4 fa0, fa1, fb;

#define LOAD_TILE()                                                            \
    {                                                                          \
        fa0 = *(const float4*)pAg;                                             \
        fa1 = *(const float4*)(pAg + 4);                                       \
        fb  = *(const float4*)pWg;                                             \
        if (FUSE_A) {                                                          \
            float4 w0 = *(const float4*)pA2g;                                  \
            float4 w1 = *(const float4*)(pA2g + 4);                            \
            fa0.x = (fa0.x - amean) * rs * w0.x;                               \
            fa0.y = (fa0.y - amean) * rs * w0.y;                               \
            fa0.z = (fa0.z - amean) * rs * w0.z;                               \
            fa0.w = (fa0.w - amean) * rs * w0.w;                               \
            fa1.x = (fa1.x - amean) * rs * w1.x;                               \
            fa1.y = (fa1.y - amean) * rs * w1.y;                               \
            fa1.z = (fa1.z - amean) * rs * w1.z;                               \
            fa1.w = (fa1.w - amean) * rs * w1.w;                               \
            pA2g += BK;                                                        \
        }                                                                      \
        pAg += BK; pWg += BK;                                                  \
    }

#define STORE_TILE(BUF)                                                        \
    {                                                                          \
        uint32_t* Ab = AsW[BUF];                                               \
        uint32_t* Bb = BsW[BUF];                                               \
        Ab[iSA[0]] = f2h2(fa0.x, fa0.y);                                       \
        Ab[iSA[1]] = f2h2(fa0.z, fa0.w);                                       \
        Ab[iSA[2]] = f2h2(fa1.x, fa1.y);                                       \
        Ab[iSA[3]] = f2h2(fa1.z, fa1.w);                                       \
        Bb[iSB[0]] = f2h2(fb.x, fb.y);                                         \
        Bb[iSB[1]] = f2h2(fb.z, fb.w);                                         \
    }

#define COMPUTE(BUF)                                                           \
    {                                                                          \
        const uint32_t* Ab = AsW[BUF];                                         \
        const uint32_t* Bb = BsW[BUF];                                         \
        uint32_t av[2][4], bv[4][2];                                           \
        _Pragma("unroll")                                                      \
        for (int mi = 0; mi < 2; mi++) {                                       \
            av[mi][0] = Ab[iA0[mi]];                                           \
            av[mi][1] = Ab[iA1[mi]];                                           \
            av[mi][2] = Ab[iA0[mi] + 512];                                     \
            av[mi][3] = Ab[iA1[mi] + 512];                                     \
        }                                                                      \
        _Pragma("unroll")                                                      \
        for (int ni = 0; ni < 4; ni++) {                                       \
            bv[ni][0] = Bb[iB0[ni]];                                           \
            bv[ni][1] = Bb[iB0[ni] + 256];                                     \
        }                                                                      \
        _Pragma("unroll")                                                      \
        for (int mi = 0; mi < 2; mi++)                                         \
        _Pragma("unroll")                                                      \
        for (int ni = 0; ni < 4; ni++)                                         \
            HMMA16816(acc[mi][ni], av[mi], bv[ni]);                            \
    }

    LOAD_TILE();
    STORE_TILE(0);
    __syncthreads();

    int nkb = K / BK;
    for (int kb = 0; kb < nkb; kb++) {
        bool more = (kb + 1 < nkb);
        if (more) LOAD_TILE();
        if (kb & 1) { COMPUTE(1); } else { COMPUTE(0); }
        if (more) {
            if (kb & 1) { STORE_TILE(0); } else { STORE_TILE(1); }
            __syncthreads();
        }
    }

#pragma unroll
    for (int mi = 0; mi < 2; mi++)
#pragma unroll
    for (int ni = 0; ni < 4; ni++) {
        int r0 = m0 + wm + mi * 16 + gid;
        int c0 = n0 + wn + ni * 8 + tig * 2;
#pragma unroll
        for (int half = 0; half < 2; half++) {
            int r = r0 + half * 8;
            if (r >= M) continue;
#pragma unroll
            for (int cc2 = 0; cc2 < 2; cc2++) {
                int c = c0 + cc2;
                if (c >= N) continue;
                float vv = acc[mi][ni][half * 2 + cc2] * alpha;
                if (HAS_BIAS) vv += bias[c];
                if (TRANS_OUT) {
                    int bidx = r / trows, q = r - bidx * trows;
                    Cp[((long long)bidx * N + c) * trows + q] = vv;
                } else {
                    Cp[(long long)r * ldc + c] = vv;
                }
            }
        }
    }
#undef LOAD_TILE
#undef STORE_TILE
#undef COMPUTE
}

// ---------------------------------------------------------------------------
// Specialized QK logits kernel (fp16 mma, Q-tile resident).
// Block = (b,h, 128 q-rows). Q (128x64, full K) resident; stream 64-row
// K-chunks double-buffered; one __syncthreads per chunk.
// ---------------------------------------------------------------------------
#define NCH ((OQ + 63) / 64)   // 13

__global__ void __launch_bounds__(256, 2)
k_qk(const float* __restrict__ Qm, const float* __restrict__ Km,
     float* __restrict__ attn) {
    __shared__ uint32_t Aq[32 * 128];     // 16 KB
    __shared__ uint32_t Bk[2][32 * 64];   // 2 x 8 KB

    int z = blockIdx.y;
    int b = z >> 3, h = z & 7;
    int q0 = blockIdx.x * 128;
    const float* Qp = Qm + (size_t)b * NQ * CC + h * HD;
    const float* Kp = Km + (size_t)b * OQ * CC + h * HD;
    float* Op = attn + (size_t)z * NQ * OQ;

    int tid = threadIdx.x;
    int lane = tid & 31, warp = tid >> 5;
    int wm = (warp & 3) * 32, wn = (warp >> 2) * 32;
    int gid = lane >> 2, tig = lane & 3;
    int rA = tid >> 1, kh = tid & 1;
    int rB = tid >> 2, kq = tid & 3;

    // resident Q tile: rows 0..127, 64 k-floats -> 32 half2 planes
    {
        int gm = min(q0 + rA, NQ - 1);
        const float* srcQ = Qp + (size_t)gm * CC + kh * 32;
#pragma unroll
        for (int j4 = 0; j4 < 8; j4++) {
            float4 v = *(const float4*)(srcQ + j4 * 4);
            int w0 = kh * 16 + j4 * 2, w1 = w0 + 1;
            Aq[w0 * 128 + (rA ^ ((w0 & 3) << 3))] = f2h2(v.x, v.y);
            Aq[w1 * 128 + (rA ^ ((w1 & 3) << 3))] = f2h2(v.z, v.w);
        }
    }

    float4 rbv[4];
#define LOADB(J)                                                               \
    {                                                                          \
        int go = min((J) * 64 + rB, OQ - 1);                                   \
        const float* src = Kp + (size_t)go * CC + kq * 16;                     \
        _Pragma("unroll")                                                      \
        for (int t = 0; t < 4; t++) rbv[t] = *(const float4*)(src + t * 4);    \
    }
#define STOREB(BUF)                                                            \
    {                                                                          \
        uint32_t* Bb = Bk[BUF];                                                \
        _Pragma("unroll")                                                      \
        for (int t = 0; t < 4; t++) {                                          \
            int w0 = kq * 8 + t * 2, w1 = w0 + 1;                              \
            Bb[w0 * 64 + (rB ^ ((w0 & 3) << 3))] = f2h2(rbv[t].x, rbv[t].y);   \
            Bb[w1 * 64 + (rB ^ ((w1 & 3) << 3))] = f2h2(rbv[t].z, rbv[t].w);   \
        }                                                                      \
    }

    uint32_t iA0[2], iA1[2], iB0[4];
#pragma unroll
    for (int mi = 0; mi < 2; mi++) {
        iA0[mi] = tig * 128 + ((wm + mi * 16 + gid) ^ (tig << 3));
        iA1[mi] = iA0[mi] ^ 8;
    }
#pragma unroll
    for (int ni = 0; ni < 4; ni++)
        iB0[ni] = tig * 64 + ((wn + ni * 8 + gid) ^ (tig << 3));

    LOADB(0);
    STOREB(0);
    __syncthreads();

    for (int j = 0; j < NCH; j++) {
        int buf = j & 1;
        bool more = (j + 1 < NCH);
        if (more) LOADB(j + 1);

        float acc[2][4][4];
#pragma unroll
        for (int i = 0; i < 2; i++)
#pragma unroll
            for (int jj = 0; jj < 4; jj++)
#pragma unroll
                for (int l = 0; l < 4; l++) acc[i][jj][l] = 0.f;

        const uint32_t* Bb = Bk[buf];
#pragma unroll
        for (int kt = 0; kt < 4; kt++) {
            uint32_t av[2][4], bv[4][2];
            int ao = kt * 1024, bo = kt * 512;
#pragma unroll
            for (int mi = 0; mi < 2; mi++) {
                av[mi][0] = Aq[ao + iA0[mi]];
                av[mi][1] = Aq[ao + iA1[mi]];
                av[mi][2] = Aq[ao + iA0[mi] + 512];
                av[mi][3] = Aq[ao + iA1[mi] + 512];
            }
#pragma unroll
            for (int ni = 0; ni < 4; ni++) {
                bv[ni][0] = Bb[bo + iB0[ni]];
                bv[ni][1] = Bb[bo + iB0[ni] + 256];
            }
#pragma unroll
            for (int mi = 0; mi < 2; mi++)
#pragma unroll
            for (int ni = 0; ni < 4; ni++)
                HMMA16816(acc[mi][ni], av[mi], bv[ni]);
        }

        int o0 = j * 64;
#pragma unroll
        for (int mi = 0; mi < 2; mi++)
#pragma unroll
        for (int ni = 0; ni < 4; ni++) {
            int r0 = q0 + wm + mi * 16 + gid;
            int c0 = o0 + wn + ni * 8 + tig * 2;
#pragma unroll
            for (int half = 0; half < 2; half++) {
                int r = r0 + half * 8;
                if (r >= NQ) continue;
#pragma unroll
                for (int cc2 = 0; cc2 < 2; cc2++) {
                    int c = c0 + cc2;
                    if (c >= OQ) continue;
                    Op[(size_t)r * OQ + c] = acc[mi][ni][half * 2 + cc2] * 0.125f;
                }
            }
        }

        if (more) {
            STOREB(buf ^ 1);
            __syncthreads();
        }
    }
#undef LOADB
#undef STOREB
}

// ---------------------------------------------------------------------------
// Fused head-mix (tc_w/tc_b) + softmax over OQ, in place on g_attn.
// ---------------------------------------------------------------------------
__global__ void __launch_bounds__(256)
k_mixsoftmax(const float* __restrict__ tcw, const float* __restrict__ tcb) {
    int bq = blockIdx.x;
    int b = bq / NQ;
    int q = bq - b * NQ;
    int tid = threadIdx.x;
    int lane = tid & 31, wid = tid >> 5;
    __shared__ float s_w[64];
    __shared__ float s_b[8];
    __shared__ float srA[8][8];
    __shared__ float srB[8][8];
    __shared__ float gmaxs[8];
    __shared__ float ginv[8];
    __shared__ float gssq[8];
    if (tid < 64) s_w[tid] = tcw[tid];
    if (tid < 8)  s_b[tid] = tcb[tid];
    __syncthreads();
    const long long HS = (long long)NQ * OQ;
    long long base0 = (long long)b * NH * HS + (long long)q * OQ;
    float m[8][4];
#pragma unroll
    for (int j = 0; j < 4; j++) {
        int o = tid + j * 256;
        bool valid = o < OQ;
        float lh[8];
#pragma unroll
        for (int h = 0; h < 8; h++)
            lh[h] = valid ? g_attn[base0 + (long long)h * HS + o] : 0.f;
#pragma unroll
        for (int g2 = 0; g2 < 8; g2++) {
            float s = s_b[g2];
#pragma unroll
            for (int h = 0; h < 8; h++) s += s_w[g2 * 8 + h] * lh[h];
            m[g2][j] = valid ? s : -1e30f;
        }
    }
    float lm[8];
#pragma unroll
    for (int g2 = 0; g2 < 8; g2++)
        lm[g2] = fmaxf(fmaxf(m[g2][0], m[g2][1]), fmaxf(m[g2][2], m[g2][3]));
#pragma unroll
    for (int off = 16; off; off >>= 1)
#pragma unroll
        for (int g2 = 0; g2 < 8; g2++)
            lm[g2] = fmaxf(lm[g2], __shfl_xor_sync(0xffffffffu, lm[g2], off));
    if (lane == 0)
#pragma unroll
        for (int g2 = 0; g2 < 8; g2++) srA[g2][wid] = lm[g2];
    __syncthreads();
    if (tid < 64) {
        float v = srA[tid >> 3][tid & 7];
        v = fmaxf(v, __shfl_xor_sync(0xffffffffu, v, 1));
        v = fmaxf(v, __shfl_xor_sync(0xffffffffu, v, 2));
        v = fmaxf(v, __shfl_xor_sync(0xffffffffu, v, 4));
        if ((tid & 7) == 0) gmaxs[tid >> 3] = v;
    }
    __syncthreads();
    float ls[8], l2[8];
#pragma unroll
    for (int g2 = 0; g2 < 8; g2++) {
        float gm_ = gmaxs[g2];
        float a = 0.f, a2 = 0.f;
#pragma unroll
        for (int j = 0; j < 4; j++) {
            float e = __expf(m[g2][j] - gm_);
            m[g2][j] = e;
            a += e; a2 += e * e;
        }
        ls[g2] = a; l2[g2] = a2;
    }
#pragma unroll
    for (int off = 16; off; off >>= 1)
#pragma unroll
        for (int g2 = 0; g2 < 8; g2++) {
            ls[g2] += __shfl_xor_sync(0xffffffffu, ls[g2], off);
            l2[g2] += __shfl_xor_sync(0xffffffffu, l2[g2], off);
        }
    if (lane == 0)
#pragma unroll
        for (int g2 = 0; g2 < 8; g2++) { srA[g2][wid] = ls[g2]; srB[g2][wid] = l2[g2]; }
    __syncthreads();
    if (tid < 64) {
        float v = srA[tid >> 3][tid & 7];
        float v2 = srB[tid >> 3][tid & 7];
        v  += __shfl_xor_sync(0xffffffffu, v, 1);
        v2 += __shfl_xor_sync(0xffffffffu, v2, 1);
        v  += __shfl_xor_sync(0xffffffffu, v, 2);
        v2 += __shfl_xor_sync(0xffffffffu, v2, 2);
        v  += __shfl_xor_sync(0xffffffffu, v, 4);
        v2 += __shfl_xor_sync(0xffffffffu, v2, 4);
        if ((tid & 7) == 0) {
            float inv = 1.f / v;
            ginv[tid >> 3] = inv;
            gssq[tid >> 3] = v2 * inv * inv;
        }
    }
    __syncthreads();
#pragma unroll
    for (int g2 = 0; g2 < 8; g2++) {
        float inv = ginv[g2];
#pragma unroll
        for (int j = 0; j < 4; j++) {
            int o = tid + j * 256;
            if (o < OQ)
                g_attn[base0 + (long long)g2 * HS + o] = m[g2][j] * inv;
        }
    }
    if (tid < 8)
        g_pssq[(long long)(b * NH + tid) * NQ + q] = gssq[tid];
}

// ---------------------------------------------------------------------------
// Finalize instance-norm rstd per (b,h)
// ---------------------------------------------------------------------------
__global__ void k_rstd() {
    int z = blockIdx.x;
    int tid = threadIdx.x;
    float s = 0.f;
    for (int i = tid; i < NQ; i += 256) s += g_pssq[(long long)z * NQ + i];
    __shared__ float r1[8];
#pragma unroll
    for (int off = 16; off; off >>= 1)
        s += __shfl_xor_sync(0xffffffffu, s, off);
    if ((tid & 31) == 0) r1[tid >> 5] = s;
    __syncthreads();
    if (tid == 0) {
        float S = 0.f;
        for (int i = 0; i < 8; i++) S += r1[i];
        const float mean = 1.f / OQ;
        float var = S / ((float)NQ * (float)OQ) - mean * mean;
        g_rstd[z] = rsqrtf(var + LEPS);
    }
}

// ---------------------------------------------------------------------------
extern "C" void kernel_launch(void* const* d_in, const int* in_sizes, int n_in,
                              void* d_out, int out_size) {
    const float* x    = (const float*)d_in[0];
    const float* aw   = (const float*)d_in[1];
    const float* q_w  = (const float*)d_in[2];
    const float* k_w  = (const float*)d_in[3];
    const float* v_w  = (const float*)d_in[4];
    const float* sr_w = (const float*)d_in[5];
    const float* sr_b = (const float*)d_in[6];
    const float* ln_g = (const float*)d_in[7];
    const float* ln_b = (const float*)d_in[8];
    const float* tc_w = (const float*)d_in[9];
    const float* tc_b = (const float*)d_in[10];
    const float* pj_w = (const float*)d_in[11];
    const float* pj_b = (const float*)d_in[12];
    float* out = (float*)d_out;

    static bool s_init = false;
    static float *p_xf, *p_xs, *p_q, *p_k, *p_vt, *p_attn, *p_ao, *p_rstd;
    if (!s_init) {
        cudaGetSymbolAddress((void**)&p_xf, g_xf);
        cudaGetSymbolAddress((void**)&p_xs, g_xs);
        cudaGetSymbolAddress((void**)&p_q, g_qb);
        cudaGetSymbolAddress((void**)&p_k, g_kb);
        cudaGetSymbolAddress((void**)&p_vt, g_vt);
        cudaGetSymbolAddress((void**)&p_attn, g_attn);
        cudaGetSymbolAddress((void**)&p_ao, g_ao);
        cudaGetSymbolAddress((void**)&p_rstd, g_rstd);
        s_init = true;
    }

    // Stage A: layouts + spatial reduction
    k_transpose<<<dim3(98, 16, 4), dim3(32, 8)>>>(x);
    k_conv<<<BB * CC, 256>>>(x, sr_w, sr_b);
    k_ln<<<BB * OQ, 256>>>(ln_g, ln_b);

    // Stage B: projections (fp16 tensor cores, fp32 accum)
    k_mma<false, false, false><<<dim3(8, 98, 1), 256>>>(
        p_xf, CC, 0, 0, q_w, CC, 0, 0, p_q, CC, 0, 0,
        BB * NQ, CC, CC, 1.f, nullptr, 0, nullptr, nullptr);
    k_mma<false, false, false><<<dim3(8, 25, 1), 256>>>(
        p_xs, CC, 0, 0, k_w, CC, 0, 0, p_k, CC, 0, 0,
        BB * OQ, CC, CC, 1.f, nullptr, 0, nullptr, nullptr);
    // V: transposed write -> g_vt (B, C, OQ)
    k_mma<true, false, false><<<dim3(8, 25, 1), 256>>>(
        p_xs, CC, 0, 0, v_w, CC, 0, 0, p_vt, 0, 0, 0,
        BB * OQ, CC, CC, 1.f, nullptr, OQ, nullptr, nullptr);

    // Stage C: specialized Q-resident QK logits kernel
    k_qk<<<dim3(25, 32), 256>>>(p_q, p_k, p_attn);

    // head-mix + softmax + instnorm stats
    k_mixsoftmax<<<BB * NQ, 256>>>(tc_w, tc_b);
    k_rstd<<<32, 256>>>();

    // Stage D: fused (instnorm * attn_weights) @ V  (V from g_vt, K-contig)
    k_mma<false, false, true><<<dim3(1, 25, 32), 256>>>(
        p_attn, OQ, (long long)NH * NQ * OQ, (long long)NQ * OQ,
        p_vt, OQ, (long long)CC * OQ, (long long)HD * OQ,
        p_ao, CC, (long long)NQ * CC, HD,
        NQ, HD, OQ, 1.f, nullptr, 0, aw, p_rstd);

    // Stage E: output projection + bias, written transposed into (B,C,HW)
    k_mma<true, true, false><<<dim3(8, 98, 1), 256>>>(
        p_ao, CC, 0, 0, pj_w, CC, 0, 0, out, 0, 0, 0,
        BB * NQ, CC, CC, 1.f, pj_b, NQ, nullptr, nullptr);
}